// round 15
// baseline (speedup 1.0000x reference)
#include <cuda_runtime.h>
#include <cstdint>

#define B_   32
#define T_   512
#define D_   512
#define H_   8
#define DK_  64
#define M_   (B_ * T_)   // 16384

// ---- scratch (no allocations allowed) ----
__device__ float g_q[M_ * D_];
__device__ float g_k[M_ * D_];
__device__ float g_v[M_ * D_];
__device__ float g_att[M_ * D_];

// ============================================================================
// tf32 helpers
// ============================================================================
__device__ __forceinline__ uint32_t f32_tf32(float x) {
    uint32_t u;
    asm("cvt.rna.tf32.f32 %0, %1;" : "=r"(u) : "f"(x));
    return u;
}
__device__ __forceinline__ float tf32f(float x) {
    uint32_t u = f32_tf32(x);
    return __uint_as_float(u);
}

__device__ __forceinline__ void mma_tf32(float c[4],
    uint32_t a0, uint32_t a1, uint32_t a2, uint32_t a3,
    uint32_t b0, uint32_t b1)
{
    asm volatile(
        "mma.sync.aligned.m16n8k8.row.col.f32.tf32.tf32.f32 "
        "{%0,%1,%2,%3}, {%4,%5,%6,%7}, {%8,%9}, {%0,%1,%2,%3};\n"
        : "+f"(c[0]), "+f"(c[1]), "+f"(c[2]), "+f"(c[3])
        : "r"(a0), "r"(a1), "r"(a2), "r"(a3), "r"(b0), "r"(b1));
}

// ============================================================================
// Projection GEMM via tf32 tensor cores (R14 passing version, unchanged).
// 128x128 block tile, BK=16, 128 threads = 4 warps (2m x 2n), warp tile 64x64.
// ============================================================================
#define GST 20

__device__ __forceinline__ void gemm_tf32_body(
    const float* __restrict__ A, const float* __restrict__ W,
    const float* __restrict__ bias, float* __restrict__ C)
{
    __shared__ __align__(16) uint32_t As[2][128][GST];
    __shared__ __align__(16) uint32_t Bs[2][128][GST];

    const int m0  = blockIdx.y * 128;
    const int n0  = blockIdx.x * 128;
    const int tid = threadIdx.x;
    const int lane = tid & 31;
    const int warp = tid >> 5;
    const int wm0 = (warp >> 1) * 64;
    const int wn0 = (warp & 1) * 64;
    const int r   = lane >> 2;
    const int cq  = lane & 3;

    const int lr  = tid >> 2;
    const int lc  = (tid & 3) << 2;

    const float* Ap = A + (size_t)(m0 + lr) * 512 + lc;
    const float* Wp = W + (size_t)(n0 + lr) * 512 + lc;

    float acc[4][8][4];
    #pragma unroll
    for (int mt = 0; mt < 4; mt++)
        #pragma unroll
        for (int nt = 0; nt < 8; nt++)
            #pragma unroll
            for (int i = 0; i < 4; i++) acc[mt][nt][i] = 0.f;

    float4 pa[4], pw[4];

    #pragma unroll
    for (int j = 0; j < 4; j++) {
        pa[j] = *(const float4*)(Ap + (size_t)(32 * j) * 512);
        pw[j] = *(const float4*)(Wp + (size_t)(32 * j) * 512);
    }
    #pragma unroll
    for (int j = 0; j < 4; j++) {
        *(uint4*)&As[0][lr + 32 * j][lc] =
            make_uint4(f32_tf32(pa[j].x), f32_tf32(pa[j].y), f32_tf32(pa[j].z), f32_tf32(pa[j].w));
        *(uint4*)&Bs[0][lr + 32 * j][lc] =
            make_uint4(f32_tf32(pw[j].x), f32_tf32(pw[j].y), f32_tf32(pw[j].z), f32_tf32(pw[j].w));
    }
    __syncthreads();

    #pragma unroll 2
    for (int k0 = 0; k0 < 512; k0 += 16) {
        const int buf = (k0 >> 4) & 1;
        const bool has_next = (k0 + 16) < 512;

        if (has_next) {
            #pragma unroll
            for (int j = 0; j < 4; j++) {
                pa[j] = *(const float4*)(Ap + (size_t)(32 * j) * 512 + k0 + 16);
                pw[j] = *(const float4*)(Wp + (size_t)(32 * j) * 512 + k0 + 16);
            }
        }

        #pragma unroll
        for (int ks = 0; ks < 2; ks++) {
            const int kb = ks * 8;
            uint32_t af[4][4];
            #pragma unroll
            for (int mt = 0; mt < 4; mt++) {
                const int mb = wm0 + mt * 16;
                af[mt][0] = As[buf][mb + r]    [kb + cq];
                af[mt][1] = As[buf][mb + r + 8][kb + cq];
                af[mt][2] = As[buf][mb + r]    [kb + cq + 4];
                af[mt][3] = As[buf][mb + r + 8][kb + cq + 4];
            }
            uint32_t bf[8][2];
            #pragma unroll
            for (int nt = 0; nt < 8; nt++) {
                const int nb = wn0 + nt * 8;
                bf[nt][0] = Bs[buf][nb + r][kb + cq];
                bf[nt][1] = Bs[buf][nb + r][kb + cq + 4];
            }
            #pragma unroll
            for (int mt = 0; mt < 4; mt++)
                #pragma unroll
                for (int nt = 0; nt < 8; nt++)
                    mma_tf32(acc[mt][nt], af[mt][0], af[mt][1], af[mt][2], af[mt][3],
                             bf[nt][0], bf[nt][1]);
        }

        if (has_next) {
            const int nb = buf ^ 1;
            #pragma unroll
            for (int j = 0; j < 4; j++) {
                *(uint4*)&As[nb][lr + 32 * j][lc] =
                    make_uint4(f32_tf32(pa[j].x), f32_tf32(pa[j].y), f32_tf32(pa[j].z), f32_tf32(pa[j].w));
                *(uint4*)&Bs[nb][lr + 32 * j][lc] =
                    make_uint4(f32_tf32(pw[j].x), f32_tf32(pw[j].y), f32_tf32(pw[j].z), f32_tf32(pw[j].w));
            }
        }
        __syncthreads();
    }

    #pragma unroll
    for (int nt = 0; nt < 8; nt++) {
        const int n = n0 + wn0 + nt * 8 + 2 * cq;
        const float2 bv = *(const float2*)(bias + n);
        #pragma unroll
        for (int mt = 0; mt < 4; mt++) {
            const int row = m0 + wm0 + mt * 16 + r;
            float2 o0, o1;
            o0.x = acc[mt][nt][0] + bv.x; o0.y = acc[mt][nt][1] + bv.y;
            o1.x = acc[mt][nt][2] + bv.x; o1.y = acc[mt][nt][3] + bv.y;
            *(float2*)(C + (size_t)row * 512 + n)       = o0;
            *(float2*)(C + (size_t)(row + 8) * 512 + n) = o1;
        }
    }
}

__global__ __launch_bounds__(128, 2) void qkv_gemm(
    const float* __restrict__ A,
    const float* __restrict__ Wq, const float* __restrict__ bq,
    const float* __restrict__ Wk, const float* __restrict__ bk,
    const float* __restrict__ Wv, const float* __restrict__ bv,
    float* __restrict__ Cq, float* __restrict__ Ck, float* __restrict__ Cv)
{
    const int z = blockIdx.z;
    const float* W    = (z == 0) ? Wq : (z == 1) ? Wk : Wv;
    const float* bias = (z == 0) ? bq : (z == 1) ? bk : bv;
    float*       C    = (z == 0) ? Cq : (z == 1) ? Ck : Cv;
    gemm_tf32_body(A, W, bias, C);
}

__global__ __launch_bounds__(128, 2) void out_gemm(
    const float* __restrict__ A, const float* __restrict__ W,
    const float* __restrict__ bias, float* __restrict__ C)
{
    gemm_tf32_body(A, W, bias, C);
}

// ============================================================================
// Tensor-core flash attention, 256-query tile (512 threads = 16 warps),
// register-resident P. Warp w owns query rows [w*16, w*16+16) x 64 keys.
// K/V staging + barriers amortized over 2x the MMA work vs the 128-query
// version; K/V L2 traffic halves (2 stages per (b,h) instead of 4).
// ============================================================================
#define KS_STR 68
#define VS_STR 72

__global__ __launch_bounds__(512, 1) void attn_tc(
    const float* __restrict__ Q, const float* __restrict__ Kg,
    const float* __restrict__ Vg,
    const float* __restrict__ rel,           // [1023, 8]
    const unsigned int* __restrict__ kpm,    // [B, T], nonzero word => masked
    float* __restrict__ out)                 // [B, T, H, DK]
{
    __shared__ __align__(16) float Ks[64 * KS_STR];
    __shared__ __align__(16) float Vs[64 * VS_STR];
    __shared__ float bias_s[320];
    __shared__ float mask_s[64];

    const int bh = blockIdx.y;
    const int b  = bh >> 3;
    const int h  = bh & 7;
    const int q0 = blockIdx.x * 256;
    const int tid  = threadIdx.x;
    const int lane = tid & 31;
    const int warp = tid >> 5;      // 0..15
    const int r  = lane >> 2;       // 0..7
    const int cq = lane & 3;        // 0..3
    const int wm = warp * 16;       // query stripe base (local, 0..240)

    const int sr = tid >> 3;            // staging row 0..63
    const int sc = (tid & 7) * 8;       // staging col chunk (8 floats)

    // ---- Q fragments straight from gmem (one time) ----
    const float* qg = Q + ((size_t)(b * T_ + q0)) * D_ + h * DK_;
    uint32_t qf[8][4];
    #pragma unroll
    for (int ks = 0; ks < 8; ks++) {
        qf[ks][0] = f32_tf32(qg[(size_t)(wm + r)     * D_ + ks * 8 + cq]);
        qf[ks][1] = f32_tf32(qg[(size_t)(wm + r + 8) * D_ + ks * 8 + cq]);
        qf[ks][2] = f32_tf32(qg[(size_t)(wm + r)     * D_ + ks * 8 + cq + 4]);
        qf[ks][3] = f32_tf32(qg[(size_t)(wm + r + 8) * D_ + ks * 8 + cq + 4]);
    }

    float m0 = -1e30f, m1 = -1e30f, l0 = 0.f, l1 = 0.f;
    float oacc[8][4];
    #pragma unroll
    for (int nt = 0; nt < 8; nt++)
        #pragma unroll
        for (int i = 0; i < 4; i++) oacc[nt][i] = 0.f;

    const int srcA = (lane & ~3) | (cq >> 1);
    const int srcB = srcA + 2;
    const bool odd = (cq & 1);

    for (int kt = 0; kt < 8; kt++) {
        const int k0 = kt * 64;
        __syncthreads();   // prior tile's Ks/Vs reads complete

        // ---- stage K (stride 68) / V (stride 72), tf32-rounded ----
        const float* kg = Kg + ((size_t)(b * T_ + k0)) * D_ + h * DK_;
        const float* vg = Vg + ((size_t)(b * T_ + k0)) * D_ + h * DK_;
        #pragma unroll
        for (int c = 0; c < 2; c++) {
            float4 kv = *(const float4*)(kg + (size_t)sr * D_ + sc + c * 4);
            float4 kt4;
            kt4.x = tf32f(kv.x); kt4.y = tf32f(kv.y);
            kt4.z = tf32f(kv.z); kt4.w = tf32f(kv.w);
            *(float4*)&Ks[sr * KS_STR + sc + c * 4] = kt4;
            float4 vv = *(const float4*)(vg + (size_t)sr * D_ + sc + c * 4);
            float4 vt4;
            vt4.x = tf32f(vv.x); vt4.y = tf32f(vv.y);
            vt4.z = tf32f(vv.z); vt4.w = tf32f(vv.w);
            *(float4*)&Vs[sr * VS_STR + sc + c * 4] = vt4;
        }
        // bias LUT: diff = k - q in [k0-q0-255, k0-q0+63] -> 319 entries
        if (tid < 319)
            bias_s[tid] = __ldg(&rel[(k0 - q0 - 255 + tid + 511) * 8 + h]);
        if (tid < 64)
            mask_s[tid] = __ldg(&kpm[b * T_ + k0 + tid]) ? -2e30f : 0.f;
        __syncthreads();

        // ---- S = Q K^T ----
        float sacc[8][4];
        #pragma unroll
        for (int nt = 0; nt < 8; nt++)
            #pragma unroll
            for (int i = 0; i < 4; i++) sacc[nt][i] = 0.f;

        #pragma unroll
        for (int ks = 0; ks < 8; ks++) {
            #pragma unroll
            for (int nt = 0; nt < 8; nt++) {
                uint32_t b0 = __float_as_uint(Ks[(nt * 8 + r) * KS_STR + ks * 8 + cq]);
                uint32_t b1 = __float_as_uint(Ks[(nt * 8 + r) * KS_STR + ks * 8 + cq + 4]);
                mma_tf32(sacc[nt], qf[ks][0], qf[ks][1], qf[ks][2], qf[ks][3], b0, b1);
            }
        }

        // ---- scale + bias + mask (f32) ----
        const int rr0 = wm + r, rr1 = wm + r + 8;
        #pragma unroll
        for (int nt = 0; nt < 8; nt++) {
            const int cc = nt * 8 + 2 * cq;
            const float mk0 = mask_s[cc], mk1 = mask_s[cc + 1];
            sacc[nt][0] = fmaf(sacc[nt][0], 0.125f, bias_s[cc     - rr0 + 255] + mk0);
            sacc[nt][1] = fmaf(sacc[nt][1], 0.125f, bias_s[cc + 1 - rr0 + 255] + mk1);
            sacc[nt][2] = fmaf(sacc[nt][2], 0.125f, bias_s[cc     - rr1 + 255] + mk0);
            sacc[nt][3] = fmaf(sacc[nt][3], 0.125f, bias_s[cc + 1 - rr1 + 255] + mk1);
        }

        // ---- online softmax (rows r / r+8, quad reduction) ----
        float rm0 = -1e30f, rm1 = -1e30f;
        #pragma unroll
        for (int nt = 0; nt < 8; nt++) {
            rm0 = fmaxf(rm0, fmaxf(sacc[nt][0], sacc[nt][1]));
            rm1 = fmaxf(rm1, fmaxf(sacc[nt][2], sacc[nt][3]));
        }
        rm0 = fmaxf(rm0, __shfl_xor_sync(0xffffffffu, rm0, 1));
        rm0 = fmaxf(rm0, __shfl_xor_sync(0xffffffffu, rm0, 2));
        rm1 = fmaxf(rm1, __shfl_xor_sync(0xffffffffu, rm1, 1));
        rm1 = fmaxf(rm1, __shfl_xor_sync(0xffffffffu, rm1, 2));

        const float mn0 = fmaxf(m0, rm0), mn1 = fmaxf(m1, rm1);
        const float al0 = __expf(m0 - mn0), al1 = __expf(m1 - mn1);
        m0 = mn0; m1 = mn1;

        float rs0 = 0.f, rs1 = 0.f;
        #pragma unroll
        for (int nt = 0; nt < 8; nt++) {
            sacc[nt][0] = __expf(sacc[nt][0] - mn0);
            sacc[nt][1] = __expf(sacc[nt][1] - mn0);
            sacc[nt][2] = __expf(sacc[nt][2] - mn1);
            sacc[nt][3] = __expf(sacc[nt][3] - mn1);
            rs0 += sacc[nt][0] + sacc[nt][1];
            rs1 += sacc[nt][2] + sacc[nt][3];
        }
        rs0 += __shfl_xor_sync(0xffffffffu, rs0, 1);
        rs0 += __shfl_xor_sync(0xffffffffu, rs0, 2);
        rs1 += __shfl_xor_sync(0xffffffffu, rs1, 1);
        rs1 += __shfl_xor_sync(0xffffffffu, rs1, 2);
        l0 = l0 * al0 + rs0;
        l1 = l1 * al1 + rs1;
        #pragma unroll
        for (int nt = 0; nt < 8; nt++) {
            oacc[nt][0] *= al0; oacc[nt][1] *= al0;
            oacc[nt][2] *= al1; oacc[nt][3] *= al1;
            sacc[nt][0] = tf32f(sacc[nt][0]);
            sacc[nt][1] = tf32f(sacc[nt][1]);
            sacc[nt][2] = tf32f(sacc[nt][2]);
            sacc[nt][3] = tf32f(sacc[nt][3]);
        }

        // ---- O += P V ; P A-fragments via quad shuffles ----
        #pragma unroll
        for (int ks = 0; ks < 8; ks++) {
            float vA0 = __shfl_sync(0xffffffffu, sacc[ks][0], srcA);
            float vA1 = __shfl_sync(0xffffffffu, sacc[ks][1], srcA);
            float vA2 = __shfl_sync(0xffffffffu, sacc[ks][2], srcA);
            float vA3 = __shfl_sync(0xffffffffu, sacc[ks][3], srcA);
            float vB0 = __shfl_sync(0xffffffffu, sacc[ks][0], srcB);
            float vB1 = __shfl_sync(0xffffffffu, sacc[ks][1], srcB);
            float vB2 = __shfl_sync(0xffffffffu, sacc[ks][2], srcB);
            float vB3 = __shfl_sync(0xffffffffu, sacc[ks][3], srcB);
            uint32_t a0 = __float_as_uint(odd ? vA1 : vA0);
            uint32_t a1 = __float_as_uint(odd ? vA3 : vA2);
            uint32_t a2 = __float_as_uint(odd ? vB1 : vB0);
            uint32_t a3 = __float_as_uint(odd ? vB3 : vB2);
            #pragma unroll
            for (int nt = 0; nt < 8; nt++) {
                uint32_t b0 = __float_as_uint(Vs[(ks * 8 + cq)     * VS_STR + nt * 8 + r]);
                uint32_t b1 = __float_as_uint(Vs[(ks * 8 + cq + 4) * VS_STR + nt * 8 + r]);
                mma_tf32(oacc[nt], a0, a1, a2, a3, b0, b1);
            }
        }
    }

    // ---- epilogue: normalize and store ----
    const float inv0 = 1.f / l0, inv1 = 1.f / l1;
    const int row0 = b * T_ + q0 + wm + r;
    #pragma unroll
    for (int nt = 0; nt < 8; nt++) {
        const int col = h * DK_ + nt * 8 + 2 * cq;
        float2 o0, o1;
        o0.x = oacc[nt][0] * inv0; o0.y = oacc[nt][1] * inv0;
        o1.x = oacc[nt][2] * inv1; o1.y = oacc[nt][3] * inv1;
        *(float2*)(out + (size_t)row0 * D_ + col)       = o0;
        *(float2*)(out + (size_t)(row0 + 8) * D_ + col) = o1;
    }
}

// ============================================================================
extern "C" void kernel_launch(void* const* d_in, const int* in_sizes, int n_in,
                              void* d_out, int out_size)
{
    const float* x   = (const float*)d_in[0];
    const float* Wq  = (const float*)d_in[1];
    const float* bq  = (const float*)d_in[2];
    const float* Wk  = (const float*)d_in[3];
    const float* bk  = (const float*)d_in[4];
    const float* Wv  = (const float*)d_in[5];
    const float* bv  = (const float*)d_in[6];
    const float* Wo  = (const float*)d_in[7];
    const float* bo  = (const float*)d_in[8];
    const float* rel = (const float*)d_in[9];
    const unsigned int* kpm = (const unsigned int*)d_in[10];
    float* out = (float*)d_out;

    float *qp, *kp, *vp, *ap;
    cudaGetSymbolAddress((void**)&qp, g_q);
    cudaGetSymbolAddress((void**)&kp, g_k);
    cudaGetSymbolAddress((void**)&vp, g_v);
    cudaGetSymbolAddress((void**)&ap, g_att);

    dim3 qkv_grid(D_ / 128, M_ / 128, 3);   // (4, 128, 3)
    qkv_gemm<<<qkv_grid, 128>>>(x, Wq, bq, Wk, bk, Wv, bv, qp, kp, vp);

    dim3 at_grid(T_ / 256, B_ * H_);        // (2, 256)
    attn_tc<<<at_grid, 512>>>(qp, kp, vp, rel, kpm, ap);

    dim3 gemm_grid(D_ / 128, M_ / 128);     // (4, 128)
    out_gemm<<<gemm_grid, 128>>>(ap, Wo, bo, out);
}

// round 16
// speedup vs baseline: 1.0203x; 1.0203x over previous
#include <cuda_runtime.h>
#include <cstdint>

#define B_   32
#define T_   512
#define D_   512
#define H_   8
#define DK_  64
#define M_   (B_ * T_)   // 16384

// ---- scratch (no allocations allowed) ----
__device__ float g_q[M_ * D_];
__device__ float g_k[M_ * D_];
__device__ float g_v[M_ * D_];
__device__ float g_att[M_ * D_];

// ============================================================================
// tf32 helpers
// ============================================================================
__device__ __forceinline__ uint32_t f32_tf32(float x) {
    uint32_t u;
    asm("cvt.rna.tf32.f32 %0, %1;" : "=r"(u) : "f"(x));
    return u;
}
__device__ __forceinline__ float tf32f(float x) {
    uint32_t u = f32_tf32(x);
    return __uint_as_float(u);
}

__device__ __forceinline__ void mma_tf32(float c[4],
    uint32_t a0, uint32_t a1, uint32_t a2, uint32_t a3,
    uint32_t b0, uint32_t b1)
{
    asm volatile(
        "mma.sync.aligned.m16n8k8.row.col.f32.tf32.tf32.f32 "
        "{%0,%1,%2,%3}, {%4,%5,%6,%7}, {%8,%9}, {%0,%1,%2,%3};\n"
        : "+f"(c[0]), "+f"(c[1]), "+f"(c[2]), "+f"(c[3])
        : "r"(a0), "r"(a1), "r"(a2), "r"(a3), "r"(b0), "r"(b1));
}

// ============================================================================
// Projection GEMM via tf32 tensor cores (R14 passing version, unchanged —
// measured at the mma.sync tf32 roofline across three configs).
// ============================================================================
#define GST 20

__device__ __forceinline__ void gemm_tf32_body(
    const float* __restrict__ A, const float* __restrict__ W,
    const float* __restrict__ bias, float* __restrict__ C)
{
    __shared__ __align__(16) uint32_t As[2][128][GST];
    __shared__ __align__(16) uint32_t Bs[2][128][GST];

    const int m0  = blockIdx.y * 128;
    const int n0  = blockIdx.x * 128;
    const int tid = threadIdx.x;
    const int lane = tid & 31;
    const int warp = tid >> 5;
    const int wm0 = (warp >> 1) * 64;
    const int wn0 = (warp & 1) * 64;
    const int r   = lane >> 2;
    const int cq  = lane & 3;

    const int lr  = tid >> 2;
    const int lc  = (tid & 3) << 2;

    const float* Ap = A + (size_t)(m0 + lr) * 512 + lc;
    const float* Wp = W + (size_t)(n0 + lr) * 512 + lc;

    float acc[4][8][4];
    #pragma unroll
    for (int mt = 0; mt < 4; mt++)
        #pragma unroll
        for (int nt = 0; nt < 8; nt++)
            #pragma unroll
            for (int i = 0; i < 4; i++) acc[mt][nt][i] = 0.f;

    float4 pa[4], pw[4];

    #pragma unroll
    for (int j = 0; j < 4; j++) {
        pa[j] = *(const float4*)(Ap + (size_t)(32 * j) * 512);
        pw[j] = *(const float4*)(Wp + (size_t)(32 * j) * 512);
    }
    #pragma unroll
    for (int j = 0; j < 4; j++) {
        *(uint4*)&As[0][lr + 32 * j][lc] =
            make_uint4(f32_tf32(pa[j].x), f32_tf32(pa[j].y), f32_tf32(pa[j].z), f32_tf32(pa[j].w));
        *(uint4*)&Bs[0][lr + 32 * j][lc] =
            make_uint4(f32_tf32(pw[j].x), f32_tf32(pw[j].y), f32_tf32(pw[j].z), f32_tf32(pw[j].w));
    }
    __syncthreads();

    #pragma unroll 2
    for (int k0 = 0; k0 < 512; k0 += 16) {
        const int buf = (k0 >> 4) & 1;
        const bool has_next = (k0 + 16) < 512;

        if (has_next) {
            #pragma unroll
            for (int j = 0; j < 4; j++) {
                pa[j] = *(const float4*)(Ap + (size_t)(32 * j) * 512 + k0 + 16);
                pw[j] = *(const float4*)(Wp + (size_t)(32 * j) * 512 + k0 + 16);
            }
        }

        #pragma unroll
        for (int ks = 0; ks < 2; ks++) {
            const int kb = ks * 8;
            uint32_t af[4][4];
            #pragma unroll
            for (int mt = 0; mt < 4; mt++) {
                const int mb = wm0 + mt * 16;
                af[mt][0] = As[buf][mb + r]    [kb + cq];
                af[mt][1] = As[buf][mb + r + 8][kb + cq];
                af[mt][2] = As[buf][mb + r]    [kb + cq + 4];
                af[mt][3] = As[buf][mb + r + 8][kb + cq + 4];
            }
            uint32_t bf[8][2];
            #pragma unroll
            for (int nt = 0; nt < 8; nt++) {
                const int nb = wn0 + nt * 8;
                bf[nt][0] = Bs[buf][nb + r][kb + cq];
                bf[nt][1] = Bs[buf][nb + r][kb + cq + 4];
            }
            #pragma unroll
            for (int mt = 0; mt < 4; mt++)
                #pragma unroll
                for (int nt = 0; nt < 8; nt++)
                    mma_tf32(acc[mt][nt], af[mt][0], af[mt][1], af[mt][2], af[mt][3],
                             bf[nt][0], bf[nt][1]);
        }

        if (has_next) {
            const int nb = buf ^ 1;
            #pragma unroll
            for (int j = 0; j < 4; j++) {
                *(uint4*)&As[nb][lr + 32 * j][lc] =
                    make_uint4(f32_tf32(pa[j].x), f32_tf32(pa[j].y), f32_tf32(pa[j].z), f32_tf32(pa[j].w));
                *(uint4*)&Bs[nb][lr + 32 * j][lc] =
                    make_uint4(f32_tf32(pw[j].x), f32_tf32(pw[j].y), f32_tf32(pw[j].z), f32_tf32(pw[j].w));
            }
        }
        __syncthreads();
    }

    #pragma unroll
    for (int nt = 0; nt < 8; nt++) {
        const int n = n0 + wn0 + nt * 8 + 2 * cq;
        const float2 bv = *(const float2*)(bias + n);
        #pragma unroll
        for (int mt = 0; mt < 4; mt++) {
            const int row = m0 + wm0 + mt * 16 + r;
            float2 o0, o1;
            o0.x = acc[mt][nt][0] + bv.x; o0.y = acc[mt][nt][1] + bv.y;
            o1.x = acc[mt][nt][2] + bv.x; o1.y = acc[mt][nt][3] + bv.y;
            *(float2*)(C + (size_t)row * 512 + n)       = o0;
            *(float2*)(C + (size_t)(row + 8) * 512 + n) = o1;
        }
    }
}

__global__ __launch_bounds__(128, 2) void qkv_gemm(
    const float* __restrict__ A,
    const float* __restrict__ Wq, const float* __restrict__ bq,
    const float* __restrict__ Wk, const float* __restrict__ bk,
    const float* __restrict__ Wv, const float* __restrict__ bv,
    float* __restrict__ Cq, float* __restrict__ Ck, float* __restrict__ Cv)
{
    const int z = blockIdx.z;
    const float* W    = (z == 0) ? Wq : (z == 1) ? Wk : Wv;
    const float* bias = (z == 0) ? bq : (z == 1) ? bk : bv;
    float*       C    = (z == 0) ? Cq : (z == 1) ? Ck : Cv;
    gemm_tf32_body(A, W, bias, C);
}

__global__ __launch_bounds__(128, 2) void out_gemm(
    const float* __restrict__ A, const float* __restrict__ W,
    const float* __restrict__ bias, float* __restrict__ C)
{
    gemm_tf32_body(A, W, bias, C);
}

// ============================================================================
// Tensor-core flash attention, 128-query tile (R14 config: 256 threads,
// 2 CTAs/SM), register-resident P. CHANGE vs R14: bias/mask LUTs are loaded
// ONCE before the key loop (full range), removing per-tile LUT staging from
// the critical section between the two barriers.
// ============================================================================
#define KS_STR 68
#define VS_STR 72

__global__ __launch_bounds__(256, 2) void attn_tc(
    const float* __restrict__ Q, const float* __restrict__ Kg,
    const float* __restrict__ Vg,
    const float* __restrict__ rel,           // [1023, 8]
    const unsigned int* __restrict__ kpm,    // [B, T], nonzero word => masked
    float* __restrict__ out)                 // [B, T, H, DK]
{
    __shared__ __align__(16) float Ks[64 * KS_STR];
    __shared__ __align__(16) float Vs[64 * VS_STR];
    __shared__ float bs[640];    // bias LUT: d = k - ql + 127, d in [0, 639)
    __shared__ float ms[512];    // mask LUT over absolute k

    const int bh = blockIdx.y;
    const int b  = bh >> 3;
    const int h  = bh & 7;
    const int q0 = blockIdx.x * 128;
    const int tid  = threadIdx.x;
    const int lane = tid & 31;
    const int warp = tid >> 5;
    const int r  = lane >> 2;
    const int cq = lane & 3;
    const int wm = warp * 16;

    const int sr = tid >> 2;
    const int sc = (tid & 3) * 16;

    // ---- Q fragments straight from gmem (one time) ----
    const float* qg = Q + ((size_t)(b * T_ + q0)) * D_ + h * DK_;
    uint32_t qf[8][4];
    #pragma unroll
    for (int ks = 0; ks < 8; ks++) {
        qf[ks][0] = f32_tf32(qg[(size_t)(wm + r)     * D_ + ks * 8 + cq]);
        qf[ks][1] = f32_tf32(qg[(size_t)(wm + r + 8) * D_ + ks * 8 + cq]);
        qf[ks][2] = f32_tf32(qg[(size_t)(wm + r)     * D_ + ks * 8 + cq + 4]);
        qf[ks][3] = f32_tf32(qg[(size_t)(wm + r + 8) * D_ + ks * 8 + cq + 4]);
    }

    // ---- full-range LUTs, loaded once ----
    // bias: for (ql, k): idx d = k - ql + 127; rel index = (d + 384 - q0)*8 + h
    for (int i = tid; i < 639; i += 256)
        bs[i] = __ldg(&rel[(i + 384 - q0) * 8 + h]);
    for (int i = tid; i < 512; i += 256)
        ms[i] = __ldg(&kpm[b * T_ + i]) ? -2e30f : 0.f;

    float m0 = -1e30f, m1 = -1e30f, l0 = 0.f, l1 = 0.f;
    float oacc[8][4];
    #pragma unroll
    for (int nt = 0; nt < 8; nt++)
        #pragma unroll
        for (int i = 0; i < 4; i++) oacc[nt][i] = 0.f;

    const int srcA = (lane & ~3) | (cq >> 1);
    const int srcB = srcA + 2;
    const bool odd = (cq & 1);

    for (int kt = 0; kt < 8; kt++) {
        const int k0 = kt * 64;
        __syncthreads();   // prior tile's Ks/Vs reads complete

        // ---- stage K (stride 68) / V (stride 72), tf32-rounded ----
        const float* kg = Kg + ((size_t)(b * T_ + k0)) * D_ + h * DK_;
        const float* vg = Vg + ((size_t)(b * T_ + k0)) * D_ + h * DK_;
        #pragma unroll
        for (int c = 0; c < 4; c++) {
            float4 kv = *(const float4*)(kg + (size_t)sr * D_ + sc + c * 4);
            float4 kt4;
            kt4.x = tf32f(kv.x); kt4.y = tf32f(kv.y);
            kt4.z = tf32f(kv.z); kt4.w = tf32f(kv.w);
            *(float4*)&Ks[sr * KS_STR + sc + c * 4] = kt4;
            float4 vv = *(const float4*)(vg + (size_t)sr * D_ + sc + c * 4);
            float4 vt4;
            vt4.x = tf32f(vv.x); vt4.y = tf32f(vv.y);
            vt4.z = tf32f(vv.z); vt4.w = tf32f(vv.w);
            *(float4*)&Vs[sr * VS_STR + sc + c * 4] = vt4;
        }
        __syncthreads();

        // ---- S = Q K^T ----
        float sacc[8][4];
        #pragma unroll
        for (int nt = 0; nt < 8; nt++)
            #pragma unroll
            for (int i = 0; i < 4; i++) sacc[nt][i] = 0.f;

        #pragma unroll
        for (int ks = 0; ks < 8; ks++) {
            #pragma unroll
            for (int nt = 0; nt < 8; nt++) {
                uint32_t b0 = __float_as_uint(Ks[(nt * 8 + r) * KS_STR + ks * 8 + cq]);
                uint32_t b1 = __float_as_uint(Ks[(nt * 8 + r) * KS_STR + ks * 8 + cq + 4]);
                mma_tf32(sacc[nt], qf[ks][0], qf[ks][1], qf[ks][2], qf[ks][3], b0, b1);
            }
        }

        // ---- scale + bias + mask (f32), LUTs pre-loaded ----
        const int rr0 = wm + r, rr1 = wm + r + 8;
        #pragma unroll
        for (int nt = 0; nt < 8; nt++) {
            const int cc = k0 + nt * 8 + 2 * cq;   // absolute key index
            const float mk0 = ms[cc], mk1 = ms[cc + 1];
            sacc[nt][0] = fmaf(sacc[nt][0], 0.125f, bs[cc     - rr0 + 127] + mk0);
            sacc[nt][1] = fmaf(sacc[nt][1], 0.125f, bs[cc + 1 - rr0 + 127] + mk1);
            sacc[nt][2] = fmaf(sacc[nt][2], 0.125f, bs[cc     - rr1 + 127] + mk0);
            sacc[nt][3] = fmaf(sacc[nt][3], 0.125f, bs[cc + 1 - rr1 + 127] + mk1);
        }

        // ---- online softmax (rows r / r+8, quad reduction) ----
        float rm0 = -1e30f, rm1 = -1e30f;
        #pragma unroll
        for (int nt = 0; nt < 8; nt++) {
            rm0 = fmaxf(rm0, fmaxf(sacc[nt][0], sacc[nt][1]));
            rm1 = fmaxf(rm1, fmaxf(sacc[nt][2], sacc[nt][3]));
        }
        rm0 = fmaxf(rm0, __shfl_xor_sync(0xffffffffu, rm0, 1));
        rm0 = fmaxf(rm0, __shfl_xor_sync(0xffffffffu, rm0, 2));
        rm1 = fmaxf(rm1, __shfl_xor_sync(0xffffffffu, rm1, 1));
        rm1 = fmaxf(rm1, __shfl_xor_sync(0xffffffffu, rm1, 2));

        const float mn0 = fmaxf(m0, rm0), mn1 = fmaxf(m1, rm1);
        const float al0 = __expf(m0 - mn0), al1 = __expf(m1 - mn1);
        m0 = mn0; m1 = mn1;

        float rs0 = 0.f, rs1 = 0.f;
        #pragma unroll
        for (int nt = 0; nt < 8; nt++) {
            sacc[nt][0] = __expf(sacc[nt][0] - mn0);
            sacc[nt][1] = __expf(sacc[nt][1] - mn0);
            sacc[nt][2] = __expf(sacc[nt][2] - mn1);
            sacc[nt][3] = __expf(sacc[nt][3] - mn1);
            rs0 += sacc[nt][0] + sacc[nt][1];
            rs1 += sacc[nt][2] + sacc[nt][3];
        }
        rs0 += __shfl_xor_sync(0xffffffffu, rs0, 1);
        rs0 += __shfl_xor_sync(0xffffffffu, rs0, 2);
        rs1 += __shfl_xor_sync(0xffffffffu, rs1, 1);
        rs1 += __shfl_xor_sync(0xffffffffu, rs1, 2);
        l0 = l0 * al0 + rs0;
        l1 = l1 * al1 + rs1;
        #pragma unroll
        for (int nt = 0; nt < 8; nt++) {
            oacc[nt][0] *= al0; oacc[nt][1] *= al0;
            oacc[nt][2] *= al1; oacc[nt][3] *= al1;
            sacc[nt][0] = tf32f(sacc[nt][0]);
            sacc[nt][1] = tf32f(sacc[nt][1]);
            sacc[nt][2] = tf32f(sacc[nt][2]);
            sacc[nt][3] = tf32f(sacc[nt][3]);
        }

        // ---- O += P V ; P A-fragments via quad shuffles ----
        #pragma unroll
        for (int ks = 0; ks < 8; ks++) {
            float vA0 = __shfl_sync(0xffffffffu, sacc[ks][0], srcA);
            float vA1 = __shfl_sync(0xffffffffu, sacc[ks][1], srcA);
            float vA2 = __shfl_sync(0xffffffffu, sacc[ks][2], srcA);
            float vA3 = __shfl_sync(0xffffffffu, sacc[ks][3], srcA);
            float vB0 = __shfl_sync(0xffffffffu, sacc[ks][0], srcB);
            float vB1 = __shfl_sync(0xffffffffu, sacc[ks][1], srcB);
            float vB2 = __shfl_sync(0xffffffffu, sacc[ks][2], srcB);
            float vB3 = __shfl_sync(0xffffffffu, sacc[ks][3], srcB);
            uint32_t a0 = __float_as_uint(odd ? vA1 : vA0);
            uint32_t a1 = __float_as_uint(odd ? vA3 : vA2);
            uint32_t a2 = __float_as_uint(odd ? vB1 : vB0);
            uint32_t a3 = __float_as_uint(odd ? vB3 : vB2);
            #pragma unroll
            for (int nt = 0; nt < 8; nt++) {
                uint32_t b0 = __float_as_uint(Vs[(ks * 8 + cq)     * VS_STR + nt * 8 + r]);
                uint32_t b1 = __float_as_uint(Vs[(ks * 8 + cq + 4) * VS_STR + nt * 8 + r]);
                mma_tf32(oacc[nt], a0, a1, a2, a3, b0, b1);
            }
        }
    }

    // ---- epilogue: normalize and store ----
    const float inv0 = 1.f / l0, inv1 = 1.f / l1;
    const int row0 = b * T_ + q0 + wm + r;
    #pragma unroll
    for (int nt = 0; nt < 8; nt++) {
        const int col = h * DK_ + nt * 8 + 2 * cq;
        float2 o0, o1;
        o0.x = oacc[nt][0] * inv0; o0.y = oacc[nt][1] * inv0;
        o1.x = oacc[nt][2] * inv1; o1.y = oacc[nt][3] * inv1;
        *(float2*)(out + (size_t)row0 * D_ + col)       = o0;
        *(float2*)(out + (size_t)(row0 + 8) * D_ + col) = o1;
    }
}

// ============================================================================
extern "C" void kernel_launch(void* const* d_in, const int* in_sizes, int n_in,
                              void* d_out, int out_size)
{
    const float* x   = (const float*)d_in[0];
    const float* Wq  = (const float*)d_in[1];
    const float* bq  = (const float*)d_in[2];
    const float* Wk  = (const float*)d_in[3];
    const float* bk  = (const float*)d_in[4];
    const float* Wv  = (const float*)d_in[5];
    const float* bv  = (const float*)d_in[6];
    const float* Wo  = (const float*)d_in[7];
    const float* bo  = (const float*)d_in[8];
    const float* rel = (const float*)d_in[9];
    const unsigned int* kpm = (const unsigned int*)d_in[10];
    float* out = (float*)d_out;

    float *qp, *kp, *vp, *ap;
    cudaGetSymbolAddress((void**)&qp, g_q);
    cudaGetSymbolAddress((void**)&kp, g_k);
    cudaGetSymbolAddress((void**)&vp, g_v);
    cudaGetSymbolAddress((void**)&ap, g_att);

    dim3 qkv_grid(D_ / 128, M_ / 128, 3);   // (4, 128, 3)
    qkv_gemm<<<qkv_grid, 128>>>(x, Wq, bq, Wk, bk, Wv, bv, qp, kp, vp);

    dim3 at_grid(T_ / 128, B_ * H_);        // (4, 256)
    attn_tc<<<at_grid, 256>>>(qp, kp, vp, rel, kpm, ap);

    dim3 gemm_grid(D_ / 128, M_ / 128);     // (4, 128)
    out_gemm<<<gemm_grid, 128>>>(ap, Wo, bo, out);
}

// round 17
// speedup vs baseline: 1.5508x; 1.5199x over previous
#include <cuda_runtime.h>
#include <cuda_fp16.h>
#include <cstdint>

#define B_   32
#define T_   512
#define D_   512
#define H_   8
#define DK_  64
#define M_   (B_ * T_)   // 16384

// ---- scratch (no allocations allowed) ----
__device__ float g_q[M_ * D_];
__device__ float g_v[M_ * D_];   // written TRANSPOSED: [(b*8+h)*64+d][t]
__device__ float g_k[M_ * D_];
__device__ float g_att[M_ * D_];

// ============================================================================
// fp16 helpers
// ============================================================================
__device__ __forceinline__ uint32_t packh2(float lo, float hi) {
    __half2 h = __floats2half2_rn(lo, hi);
    return *reinterpret_cast<uint32_t*>(&h);
}

__device__ __forceinline__ void mma_f16(float c[4],
    uint32_t a0, uint32_t a1, uint32_t a2, uint32_t a3,
    uint32_t b0, uint32_t b1)
{
    asm volatile(
        "mma.sync.aligned.m16n8k16.row.col.f32.f16.f16.f32 "
        "{%0,%1,%2,%3}, {%4,%5,%6,%7}, {%8,%9}, {%0,%1,%2,%3};\n"
        : "+f"(c[0]), "+f"(c[1]), "+f"(c[2]), "+f"(c[3])
        : "r"(a0), "r"(a1), "r"(a2), "r"(a3), "r"(b0), "r"(b1));
}

// ============================================================================
// Projection GEMM via fp16 tensor cores (m16n8k16, f32 accumulate).
// 128x128 block tile, BK=16, 128 threads = 4 warps (2m x 2n), warp tile 64x64.
// Smem: packed half2 words, [row][12 words] (8 data + 4 pad):
//   fragment loads at word (12*row + cq) -> banks 12r+cq all distinct, CF.
// TRANSC=true writes C transposed as [(b*8+h)*64+d][t] (for the V operand).
// ============================================================================
template<bool TRANSC>
__device__ __forceinline__ void gemm_f16_body(
    const float* __restrict__ A, const float* __restrict__ W,
    const float* __restrict__ bias, float* __restrict__ C)
{
    __shared__ __align__(16) uint32_t As[2][128][12];
    __shared__ __align__(16) uint32_t Bs[2][128][12];

    const int m0  = blockIdx.y * 128;
    const int n0  = blockIdx.x * 128;
    const int tid = threadIdx.x;
    const int lane = tid & 31;
    const int warp = tid >> 5;
    const int wm0 = (warp >> 1) * 64;
    const int wn0 = (warp & 1) * 64;
    const int r   = lane >> 2;
    const int cq  = lane & 3;

    const int lr  = tid >> 2;           // staging rows lr + 32j
    const int lcf = (tid & 3) * 4;      // float (k) offset
    const int lcw = (tid & 3) * 2;      // word offset

    const float* Ap = A + (size_t)(m0 + lr) * 512 + lcf;
    const float* Wp = W + (size_t)(n0 + lr) * 512 + lcf;

    float acc[4][8][4];
    #pragma unroll
    for (int mt = 0; mt < 4; mt++)
        #pragma unroll
        for (int nt = 0; nt < 8; nt++)
            #pragma unroll
            for (int i = 0; i < 4; i++) acc[mt][nt][i] = 0.f;

    float4 pa[4], pw[4];

    #pragma unroll
    for (int j = 0; j < 4; j++) {
        pa[j] = *(const float4*)(Ap + (size_t)(32 * j) * 512);
        pw[j] = *(const float4*)(Wp + (size_t)(32 * j) * 512);
    }
    #pragma unroll
    for (int j = 0; j < 4; j++) {
        *(uint2*)&As[0][lr + 32 * j][lcw] =
            make_uint2(packh2(pa[j].x, pa[j].y), packh2(pa[j].z, pa[j].w));
        *(uint2*)&Bs[0][lr + 32 * j][lcw] =
            make_uint2(packh2(pw[j].x, pw[j].y), packh2(pw[j].z, pw[j].w));
    }
    __syncthreads();

    #pragma unroll 2
    for (int k0 = 0; k0 < 512; k0 += 16) {
        const int buf = (k0 >> 4) & 1;
        const bool has_next = (k0 + 16) < 512;

        if (has_next) {
            #pragma unroll
            for (int j = 0; j < 4; j++) {
                pa[j] = *(const float4*)(Ap + (size_t)(32 * j) * 512 + k0 + 16);
                pw[j] = *(const float4*)(Wp + (size_t)(32 * j) * 512 + k0 + 16);
            }
        }

        // ---- one m16n8k16 k-step per slab ----
        uint32_t af[4][4];
        #pragma unroll
        for (int mt = 0; mt < 4; mt++) {
            const int mb = wm0 + mt * 16;
            af[mt][0] = As[buf][mb + r]    [cq];
            af[mt][1] = As[buf][mb + r + 8][cq];
            af[mt][2] = As[buf][mb + r]    [cq + 4];
            af[mt][3] = As[buf][mb + r + 8][cq + 4];
        }
        uint32_t bf[8][2];
        #pragma unroll
        for (int nt = 0; nt < 8; nt++) {
            const int nb = wn0 + nt * 8;
            bf[nt][0] = Bs[buf][nb + r][cq];
            bf[nt][1] = Bs[buf][nb + r][cq + 4];
        }
        #pragma unroll
        for (int mt = 0; mt < 4; mt++)
            #pragma unroll
            for (int nt = 0; nt < 8; nt++)
                mma_f16(acc[mt][nt], af[mt][0], af[mt][1], af[mt][2], af[mt][3],
                        bf[nt][0], bf[nt][1]);

        if (has_next) {
            const int nb = buf ^ 1;
            #pragma unroll
            for (int j = 0; j < 4; j++) {
                *(uint2*)&As[nb][lr + 32 * j][lcw] =
                    make_uint2(packh2(pa[j].x, pa[j].y), packh2(pa[j].z, pa[j].w));
                *(uint2*)&Bs[nb][lr + 32 * j][lcw] =
                    make_uint2(packh2(pw[j].x, pw[j].y), packh2(pw[j].z, pw[j].w));
            }
        }
        __syncthreads();
    }

    #pragma unroll
    for (int nt = 0; nt < 8; nt++) {
        const int n = n0 + wn0 + nt * 8 + 2 * cq;
        const float2 bv = *(const float2*)(bias + n);
        #pragma unroll
        for (int mt = 0; mt < 4; mt++) {
            const int row = m0 + wm0 + mt * 16 + r;
            if (!TRANSC) {
                float2 o0, o1;
                o0.x = acc[mt][nt][0] + bv.x; o0.y = acc[mt][nt][1] + bv.y;
                o1.x = acc[mt][nt][2] + bv.x; o1.y = acc[mt][nt][3] + bv.y;
                *(float2*)(C + (size_t)row * 512 + n)       = o0;
                *(float2*)(C + (size_t)(row + 8) * 512 + n) = o1;
            } else {
                // transposed: [(b*8+h)*64+d][t];  n = h*64+d, row = b*512+t
                const int bI = row >> 9, tl = row & 511;
                const size_t base =
                    ((size_t)(bI * 8 + (n >> 6)) * 64 + (n & 63)) * 512 + tl;
                C[base]           = acc[mt][nt][0] + bv.x;
                C[base + 512]     = acc[mt][nt][1] + bv.y;
                C[base + 8]       = acc[mt][nt][2] + bv.x;
                C[base + 512 + 8] = acc[mt][nt][3] + bv.y;
            }
        }
    }
}

__global__ __launch_bounds__(128, 2) void qkv_gemm(
    const float* __restrict__ A,
    const float* __restrict__ Wq, const float* __restrict__ bq,
    const float* __restrict__ Wk, const float* __restrict__ bk,
    const float* __restrict__ Wv, const float* __restrict__ bv,
    float* __restrict__ Cq, float* __restrict__ Ck, float* __restrict__ Cvt)
{
    const int z = blockIdx.z;
    if (z == 0)      gemm_f16_body<false>(A, Wq, bq, Cq);
    else if (z == 1) gemm_f16_body<false>(A, Wk, bk, Ck);
    else             gemm_f16_body<true >(A, Wv, bv, Cvt);
}

__global__ __launch_bounds__(128, 2) void out_gemm(
    const float* __restrict__ A, const float* __restrict__ W,
    const float* __restrict__ bias, float* __restrict__ C)
{
    gemm_f16_body<false>(A, W, bias, C);
}

// ============================================================================
// fp16 tensor-core flash attention, 128-query tile (256 threads, 2 CTAs/SM),
// register-resident P with ZERO shuffles: the f16 C-fragment of S maps
// directly onto the A-fragment of the PV mma (pack half2 of (c0,c1)/(c2,c3)).
//   Ks: [key][d] packed half2, row stride 36 words -> frag banks 4r+cq, CF.
//   Vs: [d][key] (from globally transposed V), same stride, CF.
// ============================================================================
__global__ __launch_bounds__(256, 2) void attn_tc(
    const float* __restrict__ Q, const float* __restrict__ Kg,
    const float* __restrict__ Vt,            // [(b*8+h)*64+d][t]
    const float* __restrict__ rel,           // [1023, 8]
    const unsigned int* __restrict__ kpm,    // [B, T], nonzero word => masked
    float* __restrict__ out)                 // [B, T, H, DK]
{
    __shared__ __align__(16) uint32_t Ks[64 * 36];
    __shared__ __align__(16) uint32_t Vs[64 * 36];
    __shared__ float bs[640];
    __shared__ float ms[512];

    const int bh = blockIdx.y;
    const int b  = bh >> 3;
    const int h  = bh & 7;
    const int q0 = blockIdx.x * 128;
    const int tid  = threadIdx.x;
    const int lane = tid & 31;
    const int warp = tid >> 5;
    const int r  = lane >> 2;
    const int cq = lane & 3;
    const int wm = warp * 16;

    const int sr  = tid >> 2;          // staging row (key for K, d for V)
    const int scf = (tid & 3) * 16;    // float offset within row
    const int scw = (tid & 3) * 8;     // word offset within smem row

    // ---- Q fragments straight from gmem (packed half2) ----
    const float* qg = Q + ((size_t)(b * T_ + q0)) * D_ + h * DK_;
    uint32_t qf[4][4];
    #pragma unroll
    for (int kb = 0; kb < 4; kb++) {
        const float* p0 = qg + (size_t)(wm + r) * D_ + kb * 16 + 2 * cq;
        const float* p1 = p0 + (size_t)8 * D_;
        qf[kb][0] = packh2(p0[0], p0[1]);
        qf[kb][1] = packh2(p1[0], p1[1]);
        qf[kb][2] = packh2(p0[8], p0[9]);
        qf[kb][3] = packh2(p1[8], p1[9]);
    }

    // ---- full-range LUTs, loaded once ----
    for (int i = tid; i < 639; i += 256)
        bs[i] = __ldg(&rel[(i + 384 - q0) * 8 + h]);
    for (int i = tid; i < 512; i += 256)
        ms[i] = __ldg(&kpm[b * T_ + i]) ? -2e30f : 0.f;

    float m0 = -1e30f, m1 = -1e30f, l0 = 0.f, l1 = 0.f;
    float oacc[8][4];
    #pragma unroll
    for (int nt = 0; nt < 8; nt++)
        #pragma unroll
        for (int i = 0; i < 4; i++) oacc[nt][i] = 0.f;

    for (int kt = 0; kt < 8; kt++) {
        const int k0 = kt * 64;
        __syncthreads();   // prior tile's Ks/Vs reads complete

        // ---- stage K [key][d] and Vt [d][key], fp16-packed ----
        const float* kg = Kg + (size_t)(b * T_ + k0 + sr) * D_ + h * DK_ + scf;
        const float* vg = Vt + ((size_t)((b * 8 + h) * 64 + sr)) * 512 + k0 + scf;
        {
            float4 kv0 = *(const float4*)(kg);
            float4 kv1 = *(const float4*)(kg + 4);
            float4 kv2 = *(const float4*)(kg + 8);
            float4 kv3 = *(const float4*)(kg + 12);
            *(uint4*)&Ks[36 * sr + scw] = make_uint4(
                packh2(kv0.x, kv0.y), packh2(kv0.z, kv0.w),
                packh2(kv1.x, kv1.y), packh2(kv1.z, kv1.w));
            *(uint4*)&Ks[36 * sr + scw + 4] = make_uint4(
                packh2(kv2.x, kv2.y), packh2(kv2.z, kv2.w),
                packh2(kv3.x, kv3.y), packh2(kv3.z, kv3.w));
            float4 vv0 = *(const float4*)(vg);
            float4 vv1 = *(const float4*)(vg + 4);
            float4 vv2 = *(const float4*)(vg + 8);
            float4 vv3 = *(const float4*)(vg + 12);
            *(uint4*)&Vs[36 * sr + scw] = make_uint4(
                packh2(vv0.x, vv0.y), packh2(vv0.z, vv0.w),
                packh2(vv1.x, vv1.y), packh2(vv1.z, vv1.w));
            *(uint4*)&Vs[36 * sr + scw + 4] = make_uint4(
                packh2(vv2.x, vv2.y), packh2(vv2.z, vv2.w),
                packh2(vv3.x, vv3.y), packh2(vv3.z, vv3.w));
        }
        __syncthreads();

        // ---- S = Q K^T (fp16 mma, 32 instructions) ----
        float sacc[8][4];
        #pragma unroll
        for (int nt = 0; nt < 8; nt++)
            #pragma unroll
            for (int i = 0; i < 4; i++) sacc[nt][i] = 0.f;

        #pragma unroll
        for (int kb = 0; kb < 4; kb++) {
            #pragma unroll
            for (int nt = 0; nt < 8; nt++) {
                uint32_t b0 = Ks[36 * (nt * 8 + r) + 8 * kb + cq];
                uint32_t b1 = Ks[36 * (nt * 8 + r) + 8 * kb + cq + 4];
                mma_f16(sacc[nt], qf[kb][0], qf[kb][1], qf[kb][2], qf[kb][3], b0, b1);
            }
        }

        // ---- scale + bias + mask (f32) ----
        const int rr0 = wm + r, rr1 = wm + r + 8;
        #pragma unroll
        for (int nt = 0; nt < 8; nt++) {
            const int cc = k0 + nt * 8 + 2 * cq;
            const float mk0 = ms[cc], mk1 = ms[cc + 1];
            sacc[nt][0] = fmaf(sacc[nt][0], 0.125f, bs[cc     - rr0 + 127] + mk0);
            sacc[nt][1] = fmaf(sacc[nt][1], 0.125f, bs[cc + 1 - rr0 + 127] + mk1);
            sacc[nt][2] = fmaf(sacc[nt][2], 0.125f, bs[cc     - rr1 + 127] + mk0);
            sacc[nt][3] = fmaf(sacc[nt][3], 0.125f, bs[cc + 1 - rr1 + 127] + mk1);
        }

        // ---- online softmax (rows r / r+8, quad reduction) ----
        float rm0 = -1e30f, rm1 = -1e30f;
        #pragma unroll
        for (int nt = 0; nt < 8; nt++) {
            rm0 = fmaxf(rm0, fmaxf(sacc[nt][0], sacc[nt][1]));
            rm1 = fmaxf(rm1, fmaxf(sacc[nt][2], sacc[nt][3]));
        }
        rm0 = fmaxf(rm0, __shfl_xor_sync(0xffffffffu, rm0, 1));
        rm0 = fmaxf(rm0, __shfl_xor_sync(0xffffffffu, rm0, 2));
        rm1 = fmaxf(rm1, __shfl_xor_sync(0xffffffffu, rm1, 1));
        rm1 = fmaxf(rm1, __shfl_xor_sync(0xffffffffu, rm1, 2));

        const float mn0 = fmaxf(m0, rm0), mn1 = fmaxf(m1, rm1);
        const float al0 = __expf(m0 - mn0), al1 = __expf(m1 - mn1);
        m0 = mn0; m1 = mn1;

        float rs0 = 0.f, rs1 = 0.f;
        #pragma unroll
        for (int nt = 0; nt < 8; nt++) {
            sacc[nt][0] = __expf(sacc[nt][0] - mn0);
            sacc[nt][1] = __expf(sacc[nt][1] - mn0);
            sacc[nt][2] = __expf(sacc[nt][2] - mn1);
            sacc[nt][3] = __expf(sacc[nt][3] - mn1);
            rs0 += sacc[nt][0] + sacc[nt][1];
            rs1 += sacc[nt][2] + sacc[nt][3];
        }
        rs0 += __shfl_xor_sync(0xffffffffu, rs0, 1);
        rs0 += __shfl_xor_sync(0xffffffffu, rs0, 2);
        rs1 += __shfl_xor_sync(0xffffffffu, rs1, 1);
        rs1 += __shfl_xor_sync(0xffffffffu, rs1, 2);
        l0 = l0 * al0 + rs0;
        l1 = l1 * al1 + rs1;
        #pragma unroll
        for (int nt = 0; nt < 8; nt++) {
            oacc[nt][0] *= al0; oacc[nt][1] *= al0;
            oacc[nt][2] *= al1; oacc[nt][3] *= al1;
        }

        // ---- O += P V : C-fragment packs directly into A-fragment ----
        #pragma unroll
        for (int kb = 0; kb < 4; kb++) {
            uint32_t a0 = packh2(sacc[2*kb][0],   sacc[2*kb][1]);
            uint32_t a1 = packh2(sacc[2*kb][2],   sacc[2*kb][3]);
            uint32_t a2 = packh2(sacc[2*kb+1][0], sacc[2*kb+1][1]);
            uint32_t a3 = packh2(sacc[2*kb+1][2], sacc[2*kb+1][3]);
            #pragma unroll
            for (int nt = 0; nt < 8; nt++) {
                uint32_t b0 = Vs[36 * (nt * 8 + r) + 8 * kb + cq];
                uint32_t b1 = Vs[36 * (nt * 8 + r) + 8 * kb + cq + 4];
                mma_f16(oacc[nt], a0, a1, a2, a3, b0, b1);
            }
        }
    }

    // ---- epilogue: normalize and store ----
    const float inv0 = 1.f / l0, inv1 = 1.f / l1;
    const int row0 = b * T_ + q0 + wm + r;
    #pragma unroll
    for (int nt = 0; nt < 8; nt++) {
        const int col = h * DK_ + nt * 8 + 2 * cq;
        float2 o0, o1;
        o0.x = oacc[nt][0] * inv0; o0.y = oacc[nt][1] * inv0;
        o1.x = oacc[nt][2] * inv1; o1.y = oacc[nt][3] * inv1;
        *(float2*)(out + (size_t)row0 * D_ + col)       = o0;
        *(float2*)(out + (size_t)(row0 + 8) * D_ + col) = o1;
    }
}

// ============================================================================
extern "C" void kernel_launch(void* const* d_in, const int* in_sizes, int n_in,
                              void* d_out, int out_size)
{
    const float* x   = (const float*)d_in[0];
    const float* Wq  = (const float*)d_in[1];
    const float* bq  = (const float*)d_in[2];
    const float* Wk  = (const float*)d_in[3];
    const float* bk  = (const float*)d_in[4];
    const float* Wv  = (const float*)d_in[5];
    const float* bv  = (const float*)d_in[6];
    const float* Wo  = (const float*)d_in[7];
    const float* bo  = (const float*)d_in[8];
    const float* rel = (const float*)d_in[9];
    const unsigned int* kpm = (const unsigned int*)d_in[10];
    float* out = (float*)d_out;

    float *qp, *kp, *vp, *ap;
    cudaGetSymbolAddress((void**)&qp, g_q);
    cudaGetSymbolAddress((void**)&kp, g_k);
    cudaGetSymbolAddress((void**)&vp, g_v);
    cudaGetSymbolAddress((void**)&ap, g_att);

    dim3 qkv_grid(D_ / 128, M_ / 128, 3);   // (4, 128, 3)
    qkv_gemm<<<qkv_grid, 128>>>(x, Wq, bq, Wk, bk, Wv, bv, qp, kp, vp);

    dim3 at_grid(T_ / 128, B_ * H_);        // (4, 256)
    attn_tc<<<at_grid, 256>>>(qp, kp, vp, rel, kpm, ap);

    dim3 gemm_grid(D_ / 128, M_ / 128);     // (4, 128)
    out_gemm<<<gemm_grid, 128>>>(ap, Wo, bo, out);
}